// round 2
// baseline (speedup 1.0000x reference)
#include <cuda_runtime.h>
#include <cstdint>

#define NH       128
#define ET       64          // edges per CTA tile
#define THREADS  256

typedef unsigned long long ull;

__device__ __forceinline__ ull pk2(float lo, float hi) {
    ull r; asm("mov.b64 %0, {%1, %2};" : "=l"(r) : "f"(lo), "f"(hi)); return r;
}
__device__ __forceinline__ void fma2(ull &acc, ull a, ull b) {
    asm("fma.rn.f32x2 %0, %1, %2, %0;" : "+l"(acc) : "l"(a), "l"(b));
}
__device__ __forceinline__ float2 upk(ull v) {
    float2 f; asm("mov.b64 {%0, %1}, %2;" : "=f"(f.x), "=f"(f.y) : "l"(v)); return f;
}
__device__ __forceinline__ float frelu(float v) { return fmaxf(v, 0.0f); }

// Dynamic smem layout:
//   float As[3][ET][NH]   (96 KB)  seg0 = x[row] (reused as ea2 tile for GEMM2),
//                                  seg1 = x[col], seg2 = edge_attr
//   float Ws[NH][NH]      (64 KB)  current 128x128 weight block
//   int   ridx[ET], cidx[ET]
#define SMEM_FLOATS (3*ET*NH + NH*NH)
#define SMEM_BYTES  (SMEM_FLOATS*sizeof(float) + 2*ET*sizeof(int))

__global__ void __launch_bounds__(THREADS, 1)
edge_conv_kernel(const float* __restrict__ x,
                 const float* __restrict__ eattr,
                 const int*   __restrict__ eidx,   // int32 [2, E]
                 const float* __restrict__ Wm,
                 const float* __restrict__ bm,
                 const float* __restrict__ We,
                 const float* __restrict__ be,
                 float* __restrict__ out,
                 int E, int n_nodes)
{
    extern __shared__ float sm[];
    float* As   = sm;                       // 3*ET*NH
    float* Ws   = sm + 3*ET*NH;             // NH*NH
    int*   ridx = (int*)(Ws + NH*NH);
    int*   cidx = ridx + ET;

    const int tid = threadIdx.x;
    const long long e0 = (long long)blockIdx.x * ET;

    // ---- load & clamp edge indices (int32, defensively clamped) ----
    if (tid < ET) {
        long long e = e0 + tid;
        if (e >= E) e = E - 1;
        int r = eidx[e];
        int c = eidx[(long long)E + e];
        r = min(max(r, 0), n_nodes - 1);
        c = min(max(c, 0), n_nodes - 1);
        ridx[tid] = r;
        cidx[tid] = c;
    }
    __syncthreads();

    // ---- gather the three A segments (float4 vectorized) ----
    for (int i = tid; i < ET * NH / 4; i += THREADS) {
        int e = i >> 5;               // float4s per row = 32
        int q = (i & 31) << 2;
        long long ee = e0 + e; if (ee >= E) ee = E - 1;
        *(float4*)&As[0*ET*NH + e*NH + q] =
            *(const float4*)&x[(long long)ridx[e] * NH + q];
        *(float4*)&As[1*ET*NH + e*NH + q] =
            *(const float4*)&x[(long long)cidx[e] * NH + q];
        *(float4*)&As[2*ET*NH + e*NH + q] =
            *(const float4*)&eattr[ee * NH + q];
    }

    // ---- thread tile: 4 rows x 8 cols (cols c0..c0+3 and c0+64..c0+67) ----
    const int rg = tid >> 4;          // 0..15
    const int cg = tid & 15;          // 0..15
    const int r0 = rg * 4;
    const int c0 = cg * 4;

    ull acc[4][4];
    #pragma unroll
    for (int i = 0; i < 4; i++)
        #pragma unroll
        for (int j = 0; j < 4; j++) acc[i][j] = 0ull;

    // ================= GEMM 1: three K=128 segments ===================
    for (int seg = 0; seg < 3; seg++) {
        __syncthreads();   // previous Ws fully consumed / gathers done
        {
            const float4* Wg  = (const float4*)(Wm + (long long)seg * NH * NH);
            float4*       Wsv = (float4*)Ws;
            for (int i = tid; i < NH * NH / 4; i += THREADS) Wsv[i] = Wg[i];
        }
        __syncthreads();

        const float* A = As + seg * ET * NH;
        for (int k4 = 0; k4 < NH / 4; k4++) {
            float4 av[4];
            #pragma unroll
            for (int i = 0; i < 4; i++)
                av[i] = *(const float4*)&A[(r0 + i) * NH + k4 * 4];
            #pragma unroll
            for (int kk = 0; kk < 4; kk++) {
                float4 bL = *(const float4*)&Ws[(k4*4 + kk) * NH + c0];
                float4 bH = *(const float4*)&Ws[(k4*4 + kk) * NH + c0 + 64];
                ull b0 = ((ull*)&bL)[0], b1 = ((ull*)&bL)[1];
                ull b2 = ((ull*)&bH)[0], b3 = ((ull*)&bH)[1];
                #pragma unroll
                for (int i = 0; i < 4; i++) {
                    float a = (kk == 0) ? av[i].x : (kk == 1) ? av[i].y
                            : (kk == 2) ? av[i].z : av[i].w;
                    ull ad = pk2(a, a);
                    fma2(acc[i][0], ad, b0);
                    fma2(acc[i][1], ad, b1);
                    fma2(acc[i][2], ad, b2);
                    fma2(acc[i][3], ad, b3);
                }
            }
        }
    }

    // ===== epilogue 1: ea2 = edge_attr + relu(acc + b_msg), write into As0 =====
    // Safe without extra sync: all threads passed the sync before seg2, so
    // nobody reads As0 anymore; laggards in seg2 only touch As2 + Ws.
    {
        float4 bmL = __ldg((const float4*)&bm[c0]);
        float4 bmH = __ldg((const float4*)&bm[c0 + 64]);
        #pragma unroll
        for (int i = 0; i < 4; i++) {
            int r = r0 + i;
            const float* eaRow = &As[2*ET*NH + r*NH];
            float4 eL = *(const float4*)&eaRow[c0];
            float4 eH = *(const float4*)&eaRow[c0 + 64];
            float2 p;
            float4 oL, oH;
            p = upk(acc[i][0]); oL.x = eL.x + frelu(p.x + bmL.x); oL.y = eL.y + frelu(p.y + bmL.y);
            p = upk(acc[i][1]); oL.z = eL.z + frelu(p.x + bmL.z); oL.w = eL.w + frelu(p.y + bmL.w);
            p = upk(acc[i][2]); oH.x = eH.x + frelu(p.x + bmH.x); oH.y = eH.y + frelu(p.y + bmH.y);
            p = upk(acc[i][3]); oH.z = eH.z + frelu(p.x + bmH.z); oH.w = eH.w + frelu(p.y + bmH.w);
            *(float4*)&As[r*NH + c0]      = oL;
            *(float4*)&As[r*NH + c0 + 64] = oH;
            #pragma unroll
            for (int j = 0; j < 4; j++) acc[i][j] = 0ull;
        }
    }
    __syncthreads();   // ea2 tile complete; everyone done with Ws (W_msg seg2)

    // ================= GEMM 2: K=128 over ea2 tile ===================
    {
        const float4* Wg  = (const float4*)We;
        float4*       Wsv = (float4*)Ws;
        for (int i = tid; i < NH * NH / 4; i += THREADS) Wsv[i] = Wg[i];
    }
    __syncthreads();

    for (int k4 = 0; k4 < NH / 4; k4++) {
        float4 av[4];
        #pragma unroll
        for (int i = 0; i < 4; i++)
            av[i] = *(const float4*)&As[(r0 + i) * NH + k4 * 4];
        #pragma unroll
        for (int kk = 0; kk < 4; kk++) {
            float4 bL = *(const float4*)&Ws[(k4*4 + kk) * NH + c0];
            float4 bH = *(const float4*)&Ws[(k4*4 + kk) * NH + c0 + 64];
            ull b0 = ((ull*)&bL)[0], b1 = ((ull*)&bL)[1];
            ull b2 = ((ull*)&bH)[0], b3 = ((ull*)&bH)[1];
            #pragma unroll
            for (int i = 0; i < 4; i++) {
                float a = (kk == 0) ? av[i].x : (kk == 1) ? av[i].y
                        : (kk == 2) ? av[i].z : av[i].w;
                ull ad = pk2(a, a);
                fma2(acc[i][0], ad, b0);
                fma2(acc[i][1], ad, b1);
                fma2(acc[i][2], ad, b2);
                fma2(acc[i][3], ad, b3);
            }
        }
    }

    // ===== epilogue 2: out = relu(acc + b_edge) =====
    {
        float4 beL = __ldg((const float4*)&be[c0]);
        float4 beH = __ldg((const float4*)&be[c0 + 64]);
        #pragma unroll
        for (int i = 0; i < 4; i++) {
            long long ge = e0 + r0 + i;
            if (ge >= E) continue;
            float2 p;
            float4 oL, oH;
            p = upk(acc[i][0]); oL.x = frelu(p.x + beL.x); oL.y = frelu(p.y + beL.y);
            p = upk(acc[i][1]); oL.z = frelu(p.x + beL.z); oL.w = frelu(p.y + beL.w);
            p = upk(acc[i][2]); oH.x = frelu(p.x + beH.x); oH.y = frelu(p.y + beH.y);
            p = upk(acc[i][3]); oH.z = frelu(p.x + beH.z); oH.w = frelu(p.y + beH.w);
            *(float4*)&out[ge * NH + c0]      = oL;
            *(float4*)&out[ge * NH + c0 + 64] = oH;
        }
    }
}

extern "C" void kernel_launch(void* const* d_in, const int* in_sizes, int n_in,
                              void* d_out, int out_size)
{
    const float* x     = (const float*)d_in[0];
    const float* eattr = (const float*)d_in[1];
    const int*   eidx  = (const int*)d_in[2];     // int32 (JAX canonicalizes int64->int32)
    const float* Wm    = (const float*)d_in[3];
    const float* bm    = (const float*)d_in[4];
    const float* We    = (const float*)d_in[5];
    const float* be    = (const float*)d_in[6];
    float*       out   = (float*)d_out;

    const int E       = in_sizes[2] / 2;   // edge_index is [2, E]
    const int n_nodes = in_sizes[0] / NH;

    size_t smem = SMEM_BYTES;
    cudaFuncSetAttribute(edge_conv_kernel,
                         cudaFuncAttributeMaxDynamicSharedMemorySize, (int)smem);

    dim3 grid((E + ET - 1) / ET);
    edge_conv_kernel<<<grid, THREADS, smem>>>(x, eattr, eidx, Wm, bm, We, be, out,
                                              E, n_nodes);
}

// round 4
// speedup vs baseline: 2.3769x; 2.3769x over previous
#include <cuda_runtime.h>
#include <cuda_bf16.h>
#include <cstdint>

#define NH       128
#define MT       128          // edges per CTA tile
#define THREADS  256

// ---------------- smem layout (bytes) ----------------
#define OFF_RIDX 0            // 128 ints
#define OFF_CIDX 512          // 128 ints
#define OFF_AHI  1024
#define OFF_ALO  (OFF_AHI + 32768)
#define OFF_BHI  (OFF_ALO + 32768)
#define OFF_BLO  (OFF_BHI + 32768)
#define SMEM_TOTAL (OFF_BLO + 32768)   // 132096 B

#define MAX_NODES 131072

// ---------------- device scratch (no allocs allowed) ----------------
__device__ uint4 g_xhi[MAX_NODES * 16];   // [node][128] bf16 hi (16B chunks, linear)
__device__ uint4 g_xlo[MAX_NODES * 16];
__device__ uint4 g_wimg_hi[4][2048];      // B'[n][k] bf16, swizzled 32KB images
__device__ uint4 g_wimg_lo[4][2048];

// ---------------- helpers ----------------
__device__ __forceinline__ uint32_t smem_u32(const void* p) {
    uint32_t a;
    asm("{ .reg .u64 t; cvta.to.shared.u64 t, %1; cvt.u32.u64 %0, t; }" : "=r"(a) : "l"(p));
    return a;
}
__device__ __forceinline__ float frelu(float v) { return fmaxf(v, 0.0f); }

__device__ __forceinline__ void split2(float a, float b, uint32_t& h, uint32_t& l) {
    __nv_bfloat162 hv = __floats2bfloat162_rn(a, b);
    float ha = __bfloat162float(__low2bfloat16(hv));
    float hb = __bfloat162float(__high2bfloat16(hv));
    __nv_bfloat162 lv = __floats2bfloat162_rn(a - ha, b - hb);
    h = *reinterpret_cast<uint32_t*>(&hv);
    l = *reinterpret_cast<uint32_t*>(&lv);
}

__device__ __forceinline__ void ldsm_x4(uint32_t (&r)[4], uint32_t addr) {
    asm volatile("ldmatrix.sync.aligned.m8n8.x4.shared.b16 {%0,%1,%2,%3}, [%4];"
        : "=r"(r[0]), "=r"(r[1]), "=r"(r[2]), "=r"(r[3]) : "r"(addr));
}
__device__ __forceinline__ void ldsm_x2(uint32_t (&r)[2], uint32_t addr) {
    asm volatile("ldmatrix.sync.aligned.m8n8.x2.shared.b16 {%0,%1}, [%2];"
        : "=r"(r[0]), "=r"(r[1]) : "r"(addr));
}
__device__ __forceinline__ void mma16816(float (&d)[4], const uint32_t (&a)[4],
                                         const uint32_t (&b)[2]) {
    asm volatile("mma.sync.aligned.m16n8k16.row.col.f32.bf16.bf16.f32 "
        "{%0,%1,%2,%3}, {%4,%5,%6,%7}, {%8,%9}, {%0,%1,%2,%3};"
        : "+f"(d[0]), "+f"(d[1]), "+f"(d[2]), "+f"(d[3])
        : "r"(a[0]), "r"(a[1]), "r"(a[2]), "r"(a[3]), "r"(b[0]), "r"(b[1]));
}

// ================= prep kernels =================
// B'[n][k] = W[k][n], row n = 256B, 16B chunk c placed at (c ^ (n&7))
__global__ void prep_w_kernel(const float* __restrict__ Wm, const float* __restrict__ We) {
    int idx = blockIdx.x * blockDim.x + threadIdx.x;   // < 4*16384
    if (idx >= 65536) return;
    int mat = idx >> 14, e = idx & 16383;
    int n = e >> 7, k = e & 127;
    float v = (mat < 3) ? Wm[(mat * 128 + k) * 128 + n] : We[k * 128 + n];
    __nv_bfloat16 hi = __float2bfloat16_rn(v);
    __nv_bfloat16 lo = __float2bfloat16_rn(v - __bfloat162float(hi));
    uint32_t pos = (uint32_t)(n * 256 + (((k >> 3) ^ (n & 7)) << 4) + ((k & 7) << 1));
    *(__nv_bfloat16*)((char*)g_wimg_hi[mat] + pos) = hi;
    *(__nv_bfloat16*)((char*)g_wimg_lo[mat] + pos) = lo;
}

__global__ void prep_x_kernel(const float* __restrict__ x, long long total) {
    long long idx = (long long)blockIdx.x * blockDim.x + threadIdx.x;
    if (idx >= total) return;
    float v = x[idx];
    __nv_bfloat16 hi = __float2bfloat16_rn(v);
    __nv_bfloat16 lo = __float2bfloat16_rn(v - __bfloat162float(hi));
    ((__nv_bfloat16*)g_xhi)[idx] = hi;
    ((__nv_bfloat16*)g_xlo)[idx] = lo;
}

// ================= warp GEMM: acc += A(128x128 split) @ B'(128x128 split)^T ======
// warp-tile 32 (rows, 2 m16) x 64 (cols, 8 n8); 3-term split accumulate.
__device__ __forceinline__ void do_gemm(uint32_t sb, float (&acc)[2][8][4],
                                        int wm, int wn, int lane) {
    const int sx = lane & 7;
    const int aR = 32 * wm + sx + ((lane >> 3) & 1) * 8;
    const int aK = (lane >> 4) & 1;
    const int bR = 64 * wn + sx;
    const int bK = (lane >> 3) & 1;
    const uint32_t aBase = sb + OFF_AHI + (uint32_t)aR * 256;
    const uint32_t bBase = sb + OFF_BHI + (uint32_t)bR * 256;

    #pragma unroll 2
    for (int ks = 0; ks < 8; ks++) {
        uint32_t ah[2][4], al[2][4];
        #pragma unroll
        for (int mt = 0; mt < 2; mt++) {
            uint32_t off = (uint32_t)(mt * 16 * 256) + ((uint32_t)((2 * ks + aK) ^ sx) << 4);
            ldsm_x4(ah[mt], aBase + off);
            ldsm_x4(al[mt], aBase + off + (OFF_ALO - OFF_AHI));
        }
        #pragma unroll
        for (int nt = 0; nt < 8; nt++) {
            uint32_t off = (uint32_t)(nt * 8 * 256) + ((uint32_t)((2 * ks + bK) ^ sx) << 4);
            uint32_t bh[2], bl[2];
            ldsm_x2(bh, bBase + off);
            ldsm_x2(bl, bBase + off + (OFF_BLO - OFF_BHI));
            #pragma unroll
            for (int mt = 0; mt < 2; mt++) {
                mma16816(acc[mt][nt], ah[mt], bh);
                mma16816(acc[mt][nt], al[mt], bh);
                mma16816(acc[mt][nt], ah[mt], bl);
            }
        }
    }
}

// ================= main fused kernel =================
__global__ void __launch_bounds__(THREADS, 1)
edge_conv_mma(const float* __restrict__ eattr,
              const int*   __restrict__ eidx,
              const float* __restrict__ bm,
              const float* __restrict__ be,
              float* __restrict__ out,
              int E, int n_nodes)
{
    extern __shared__ char smc[];
    const uint32_t sb = smem_u32(smc);
    int* ridx = (int*)(smc + OFF_RIDX);
    int* cidx = (int*)(smc + OFF_CIDX);

    const int tid  = threadIdx.x;
    const int wid  = tid >> 5;
    const int lane = tid & 31;
    const int wm   = wid & 3;          // row group (32 edges)
    const int wn   = wid >> 2;         // col group (64 cols)
    const long long e0 = (long long)blockIdx.x * MT;

    if (tid < MT) {
        long long e = e0 + tid; if (e >= E) e = E - 1;
        int r = eidx[e];
        int c = eidx[(long long)E + e];
        ridx[tid] = min(max(r, 0), n_nodes - 1);
        cidx[tid] = min(max(c, 0), n_nodes - 1);
    }

    float acc[2][8][4];
    #pragma unroll
    for (int i = 0; i < 2; i++)
        #pragma unroll
        for (int j = 0; j < 8; j++)
            #pragma unroll
            for (int q = 0; q < 4; q++) acc[i][j][q] = 0.0f;

    // =========== GEMM 1: three K=128 segments ===========
    for (int seg = 0; seg < 3; seg++) {
        __syncthreads();   // prior A/B fully consumed (and idx ready on seg 0)
        // --- stage A tile ---
        if (seg < 2) {
            const int* idxa = (seg == 0) ? ridx : cidx;
            for (int i = tid; i < MT * 16; i += THREADS) {
                int e = i >> 4, c = i & 15;
                int node = idxa[e];
                uint4 vh = g_xhi[node * 16 + c];
                uint4 vl = g_xlo[node * 16 + c];
                uint32_t off = (uint32_t)(e * 256 + ((c ^ (e & 7)) << 4));
                *(uint4*)(smc + OFF_AHI + off) = vh;
                *(uint4*)(smc + OFF_ALO + off) = vl;
            }
        } else {
            for (int i = tid; i < MT * 16; i += THREADS) {
                int e = i >> 4, c = i & 15;
                long long ge = e0 + e; if (ge >= E) ge = E - 1;
                const float4* s = (const float4*)(eattr + ge * NH + c * 8);
                float4 fa = __ldg(s), fb = __ldg(s + 1);
                uint4 h, l;
                split2(fa.x, fa.y, h.x, l.x);
                split2(fa.z, fa.w, h.y, l.y);
                split2(fb.x, fb.y, h.z, l.z);
                split2(fb.z, fb.w, h.w, l.w);
                uint32_t off = (uint32_t)(e * 256 + ((c ^ (e & 7)) << 4));
                *(uint4*)(smc + OFF_AHI + off) = h;
                *(uint4*)(smc + OFF_ALO + off) = l;
            }
        }
        // --- stage B tile (linear copy of preswizzled image) ---
        {
            const uint4* ih = g_wimg_hi[seg];
            const uint4* il = g_wimg_lo[seg];
            uint4* oh = (uint4*)(smc + OFF_BHI);
            uint4* ol = (uint4*)(smc + OFF_BLO);
            for (int i = tid; i < 2048; i += THREADS) { oh[i] = ih[i]; ol[i] = il[i]; }
        }
        __syncthreads();
        do_gemm(sb, acc, wm, wn, lane);
    }

    __syncthreads();   // all warps done reading A/B of GEMM1

    // =========== epilogue 1: ea2 = eattr + relu(msg + bm), RMW A tiles in place =====
    {
        const int rq = lane >> 2;          // 0..7
        const int cq = (lane & 3) * 2;     // 0,2,4,6
        #pragma unroll
        for (int mt = 0; mt < 2; mt++) {
            int row0 = 32 * wm + 16 * mt + rq;
            #pragma unroll
            for (int nt = 0; nt < 8; nt++) {
                int c = 64 * wn + 8 * nt + cq;
                float2 bmv = __ldg((const float2*)(bm + c));
                #pragma unroll
                for (int h = 0; h < 2; h++) {
                    int row = row0 + 8 * h;
                    uint32_t addr = (uint32_t)(row * 256 +
                                    (((c >> 3) ^ (row & 7)) << 4) + ((c & 7) << 1));
                    uint32_t hu = *(uint32_t*)(smc + OFF_AHI + addr);
                    uint32_t lu = *(uint32_t*)(smc + OFF_ALO + addr);
                    __nv_bfloat162 hb = *(__nv_bfloat162*)&hu;
                    __nv_bfloat162 lb = *(__nv_bfloat162*)&lu;
                    float ev0 = __bfloat162float(__low2bfloat16(hb))
                              + __bfloat162float(__low2bfloat16(lb));
                    float ev1 = __bfloat162float(__high2bfloat16(hb))
                              + __bfloat162float(__high2bfloat16(lb));
                    float v0 = ev0 + frelu(acc[mt][nt][2 * h + 0] + bmv.x);
                    float v1 = ev1 + frelu(acc[mt][nt][2 * h + 1] + bmv.y);
                    uint32_t nh, nl;
                    split2(v0, v1, nh, nl);
                    *(uint32_t*)(smc + OFF_AHI + addr) = nh;
                    *(uint32_t*)(smc + OFF_ALO + addr) = nl;
                    acc[mt][nt][2 * h + 0] = 0.0f;
                    acc[mt][nt][2 * h + 1] = 0.0f;
                }
            }
        }
    }
    __syncthreads();   // ea2 tile complete across warps

    // --- stage B = W_edge image ---
    {
        const uint4* ih = g_wimg_hi[3];
        const uint4* il = g_wimg_lo[3];
        uint4* oh = (uint4*)(smc + OFF_BHI);
        uint4* ol = (uint4*)(smc + OFF_BLO);
        for (int i = tid; i < 2048; i += THREADS) { oh[i] = ih[i]; ol[i] = il[i]; }
    }
    __syncthreads();

    // =========== GEMM 2 ===========
    do_gemm(sb, acc, wm, wn, lane);

    // =========== epilogue 2: out = relu(acc + be) ===========
    {
        const int rq = lane >> 2;
        const int cq = (lane & 3) * 2;
        #pragma unroll
        for (int mt = 0; mt < 2; mt++) {
            int row0 = 32 * wm + 16 * mt + rq;
            #pragma unroll
            for (int nt = 0; nt < 8; nt++) {
                int c = 64 * wn + 8 * nt + cq;
                float2 bev = __ldg((const float2*)(be + c));
                #pragma unroll
                for (int h = 0; h < 2; h++) {
                    int row = row0 + 8 * h;
                    long long ge = e0 + row;
                    if (ge < E) {
                        float2 o;
                        o.x = frelu(acc[mt][nt][2 * h + 0] + bev.x);
                        o.y = frelu(acc[mt][nt][2 * h + 1] + bev.y);
                        *(float2*)(out + ge * NH + c) = o;
                    }
                }
            }
        }
    }
}

// ================= host =================
extern "C" void kernel_launch(void* const* d_in, const int* in_sizes, int n_in,
                              void* d_out, int out_size)
{
    const float* x     = (const float*)d_in[0];
    const float* eattr = (const float*)d_in[1];
    const int*   eidx  = (const int*)d_in[2];   // int32 (JAX canonicalizes int64->int32)
    const float* Wm    = (const float*)d_in[3];
    const float* bm    = (const float*)d_in[4];
    const float* We    = (const float*)d_in[5];
    const float* be    = (const float*)d_in[6];
    float*       out   = (float*)d_out;

    const int E  = in_sizes[2] / 2;
    int n_nodes  = in_sizes[0] / NH;
    if (n_nodes > MAX_NODES) n_nodes = MAX_NODES;

    prep_w_kernel<<<(65536 + 255) / 256, 256>>>(Wm, We);
    long long xt = (long long)n_nodes * NH;
    prep_x_kernel<<<(unsigned)((xt + 255) / 256), 256>>>(x, xt);

    cudaFuncSetAttribute(edge_conv_mma,
                         cudaFuncAttributeMaxDynamicSharedMemorySize, SMEM_TOTAL);

    dim3 grid((E + MT - 1) / MT);
    edge_conv_mma<<<grid, THREADS, SMEM_TOTAL>>>(eattr, eidx, bm, be, out, E, n_nodes);
}

// round 5
// speedup vs baseline: 3.5268x; 1.4838x over previous
#include <cuda_runtime.h>
#include <cuda_bf16.h>
#include <cstdint>

#define NH       128
#define ET       256          // edges per CTA tile
#define THREADS  256

// ---------------- smem layout (bytes) ----------------
#define OFF_RIDX 0             // 256 ints
#define OFF_CIDX 1024          // 256 ints
#define OFF_AHI  2048          // 256 rows x 256B
#define OFF_ALO  (OFF_AHI + 65536)
#define OFF_BHI  (OFF_ALO + 65536)   // 128 rows x 256B
#define OFF_BLO  (OFF_BHI + 32768)
#define SMEM_TOTAL (OFF_BLO + 32768)   // 198656 B

#define MAX_NODES 131072

// ---------------- device scratch (no allocs allowed) ----------------
__device__ uint4 g_xhi[MAX_NODES * 16];   // [node][128] bf16 hi (16B chunks, linear)
__device__ uint4 g_xlo[MAX_NODES * 16];
__device__ uint4 g_wimg_hi[4][2048];      // B'[n][k] bf16, swizzled 32KB images
__device__ uint4 g_wimg_lo[4][2048];

// ---------------- helpers ----------------
__device__ __forceinline__ uint32_t smem_u32(const void* p) {
    uint32_t a;
    asm("{ .reg .u64 t; cvta.to.shared.u64 t, %1; cvt.u32.u64 %0, t; }" : "=r"(a) : "l"(p));
    return a;
}
__device__ __forceinline__ float frelu(float v) { return fmaxf(v, 0.0f); }

__device__ __forceinline__ void split2(float a, float b, uint32_t& h, uint32_t& l) {
    __nv_bfloat162 hv = __floats2bfloat162_rn(a, b);
    float ha = __bfloat162float(__low2bfloat16(hv));
    float hb = __bfloat162float(__high2bfloat16(hv));
    __nv_bfloat162 lv = __floats2bfloat162_rn(a - ha, b - hb);
    h = *reinterpret_cast<uint32_t*>(&hv);
    l = *reinterpret_cast<uint32_t*>(&lv);
}

__device__ __forceinline__ void cp16(uint32_t smem_dst, const void* gsrc) {
    asm volatile("cp.async.cg.shared.global [%0], [%1], 16;"
                 :: "r"(smem_dst), "l"(gsrc) : "memory");
}
__device__ __forceinline__ void cp_commit_wait() {
    asm volatile("cp.async.commit_group;" ::: "memory");
    asm volatile("cp.async.wait_group 0;" ::: "memory");
}

__device__ __forceinline__ void ldsm_x4(uint32_t (&r)[4], uint32_t addr) {
    asm volatile("ldmatrix.sync.aligned.m8n8.x4.shared.b16 {%0,%1,%2,%3}, [%4];"
        : "=r"(r[0]), "=r"(r[1]), "=r"(r[2]), "=r"(r[3]) : "r"(addr));
}
__device__ __forceinline__ void ldsm_x2(uint32_t (&r)[2], uint32_t addr) {
    asm volatile("ldmatrix.sync.aligned.m8n8.x2.shared.b16 {%0,%1}, [%2];"
        : "=r"(r[0]), "=r"(r[1]) : "r"(addr));
}
__device__ __forceinline__ void mma16816(float (&d)[4], const uint32_t (&a)[4],
                                         const uint32_t (&b)[2]) {
    asm volatile("mma.sync.aligned.m16n8k16.row.col.f32.bf16.bf16.f32 "
        "{%0,%1,%2,%3}, {%4,%5,%6,%7}, {%8,%9}, {%0,%1,%2,%3};"
        : "+f"(d[0]), "+f"(d[1]), "+f"(d[2]), "+f"(d[3])
        : "r"(a[0]), "r"(a[1]), "r"(a[2]), "r"(a[3]), "r"(b[0]), "r"(b[1]));
}

// ================= prep kernels =================
// B'[n][k] = W[k][n], row n = 256B, 16B chunk c placed at (c ^ (n&7))
__global__ void prep_w_kernel(const float* __restrict__ Wm, const float* __restrict__ We) {
    int idx = blockIdx.x * blockDim.x + threadIdx.x;   // < 4*16384
    if (idx >= 65536) return;
    int mat = idx >> 14, e = idx & 16383;
    int n = e >> 7, k = e & 127;
    float v = (mat < 3) ? Wm[(mat * 128 + k) * 128 + n] : We[k * 128 + n];
    __nv_bfloat16 hi = __float2bfloat16_rn(v);
    __nv_bfloat16 lo = __float2bfloat16_rn(v - __bfloat162float(hi));
    uint32_t pos = (uint32_t)(n * 256 + (((k >> 3) ^ (n & 7)) << 4) + ((k & 7) << 1));
    *(__nv_bfloat16*)((char*)g_wimg_hi[mat] + pos) = hi;
    *(__nv_bfloat16*)((char*)g_wimg_lo[mat] + pos) = lo;
}

__global__ void prep_x_kernel(const float* __restrict__ x, long long total) {
    long long idx = (long long)blockIdx.x * blockDim.x + threadIdx.x;
    if (idx >= total) return;
    float v = x[idx];
    __nv_bfloat16 hi = __float2bfloat16_rn(v);
    __nv_bfloat16 lo = __float2bfloat16_rn(v - __bfloat162float(hi));
    ((__nv_bfloat16*)g_xhi)[idx] = hi;
    ((__nv_bfloat16*)g_xlo)[idx] = lo;
}

// ================= warp GEMM: acc += A(256x128 split) @ B'(128x128 split)^T ======
// warp-tile 64 (rows, 4 m16) x 64 (cols, 8 n8); 3-term split accumulate.
__device__ __forceinline__ void do_gemm(uint32_t sb, float (&acc)[4][8][4],
                                        int wm, int wn, int lane) {
    const int sx = lane & 7;
    const int aR = 64 * wm + sx + ((lane >> 3) & 1) * 8;
    const int aK = (lane >> 4) & 1;
    const int bR = 64 * wn + sx;
    const int bK = (lane >> 3) & 1;
    const uint32_t aBase = sb + OFF_AHI + (uint32_t)aR * 256;
    const uint32_t bBase = sb + OFF_BHI + (uint32_t)bR * 256;

    #pragma unroll 1
    for (int ks = 0; ks < 8; ks++) {
        uint32_t ah[4][4], al[4][4];
        #pragma unroll
        for (int mt = 0; mt < 4; mt++) {
            uint32_t off = (uint32_t)(mt * 16 * 256) + ((uint32_t)((2 * ks + aK) ^ sx) << 4);
            ldsm_x4(ah[mt], aBase + off);
            ldsm_x4(al[mt], aBase + off + (OFF_ALO - OFF_AHI));
        }
        #pragma unroll
        for (int nt = 0; nt < 8; nt++) {
            uint32_t off = (uint32_t)(nt * 8 * 256) + ((uint32_t)((2 * ks + bK) ^ sx) << 4);
            uint32_t bh[2], bl[2];
            ldsm_x2(bh, bBase + off);
            ldsm_x2(bl, bBase + off + (OFF_BLO - OFF_BHI));
            #pragma unroll
            for (int mt = 0; mt < 4; mt++) {
                mma16816(acc[mt][nt], ah[mt], bh);
                mma16816(acc[mt][nt], al[mt], bh);
                mma16816(acc[mt][nt], ah[mt], bl);
            }
        }
    }
}

// ================= main fused kernel =================
__global__ void __launch_bounds__(THREADS, 1)
edge_conv_mma(const float* __restrict__ eattr,
              const int*   __restrict__ eidx,
              const float* __restrict__ bm,
              const float* __restrict__ be,
              float* __restrict__ out,
              int E, int n_nodes)
{
    extern __shared__ char smc[];
    const uint32_t sb = smem_u32(smc);
    int* ridx = (int*)(smc + OFF_RIDX);
    int* cidx = (int*)(smc + OFF_CIDX);

    const int tid  = threadIdx.x;
    const int wid  = tid >> 5;
    const int lane = tid & 31;
    const int wm   = wid & 3;          // row group (64 edges)
    const int wn   = wid >> 2;         // col group (64 cols)
    const long long e0 = (long long)blockIdx.x * ET;

    {
        long long e = e0 + tid; if (e >= E) e = E - 1;
        int r = eidx[e];
        int c = eidx[(long long)E + e];
        ridx[tid] = min(max(r, 0), n_nodes - 1);
        cidx[tid] = min(max(c, 0), n_nodes - 1);
    }

    float acc[4][8][4];
    #pragma unroll
    for (int i = 0; i < 4; i++)
        #pragma unroll
        for (int j = 0; j < 8; j++)
            #pragma unroll
            for (int q = 0; q < 4; q++) acc[i][j][q] = 0.0f;

    // =========== GEMM 1: three K=128 segments ===========
    for (int seg = 0; seg < 3; seg++) {
        __syncthreads();   // prior A/B consumed; idx visible on seg 0
        // --- stage A tile ---
        if (seg < 2) {
            const int* idxa = (seg == 0) ? ridx : cidx;
            #pragma unroll
            for (int it = 0; it < 16; it++) {
                int i = tid + it * THREADS;          // < 4096
                int e = i >> 4, c = i & 15;
                int node = idxa[e];
                uint32_t off = (uint32_t)(e * 256 + ((c ^ (e & 7)) << 4));
                cp16(sb + OFF_AHI + off, &g_xhi[node * 16 + c]);
                cp16(sb + OFF_ALO + off, &g_xlo[node * 16 + c]);
            }
        } else {
            #pragma unroll 4
            for (int it = 0; it < 16; it++) {
                int i = tid + it * THREADS;
                int e = i >> 4, c = i & 15;
                long long ge = e0 + e; if (ge >= E) ge = E - 1;
                const float4* s = (const float4*)(eattr + ge * NH + c * 8);
                float4 fa = __ldg(s), fb = __ldg(s + 1);
                uint4 h, l;
                split2(fa.x, fa.y, h.x, l.x);
                split2(fa.z, fa.w, h.y, l.y);
                split2(fb.x, fb.y, h.z, l.z);
                split2(fb.z, fb.w, h.w, l.w);
                uint32_t off = (uint32_t)(e * 256 + ((c ^ (e & 7)) << 4));
                *(uint4*)(smc + OFF_AHI + off) = h;
                *(uint4*)(smc + OFF_ALO + off) = l;
            }
        }
        // --- stage B tile (cp.async of preswizzled image) ---
        #pragma unroll
        for (int it = 0; it < 8; it++) {
            int i = tid + it * THREADS;              // < 2048
            cp16(sb + OFF_BHI + i * 16, &g_wimg_hi[seg][i]);
            cp16(sb + OFF_BLO + i * 16, &g_wimg_lo[seg][i]);
        }
        cp_commit_wait();
        __syncthreads();
        do_gemm(sb, acc, wm, wn, lane);
    }

    __syncthreads();   // all warps done reading A/B of GEMM1

    // --- stage B = W_edge image (async; overlaps epilogue 1) ---
    #pragma unroll
    for (int it = 0; it < 8; it++) {
        int i = tid + it * THREADS;
        cp16(sb + OFF_BHI + i * 16, &g_wimg_hi[3][i]);
        cp16(sb + OFF_BLO + i * 16, &g_wimg_lo[3][i]);
    }
    asm volatile("cp.async.commit_group;" ::: "memory");

    // =========== epilogue 1: ea2 = eattr + relu(msg + bm), RMW A tiles in place =====
    {
        const int rq = lane >> 2;          // 0..7
        const int cq = (lane & 3) * 2;     // 0,2,4,6
        #pragma unroll
        for (int mt = 0; mt < 4; mt++) {
            int row0 = 64 * wm + 16 * mt + rq;
            #pragma unroll
            for (int nt = 0; nt < 8; nt++) {
                int c = 64 * wn + 8 * nt + cq;
                float2 bmv = __ldg((const float2*)(bm + c));
                #pragma unroll
                for (int h = 0; h < 2; h++) {
                    int row = row0 + 8 * h;
                    uint32_t addr = (uint32_t)(row * 256 +
                                    (((c >> 3) ^ (row & 7)) << 4) + ((c & 7) << 1));
                    uint32_t hu = *(uint32_t*)(smc + OFF_AHI + addr);
                    uint32_t lu = *(uint32_t*)(smc + OFF_ALO + addr);
                    __nv_bfloat162 hb = *(__nv_bfloat162*)&hu;
                    __nv_bfloat162 lb = *(__nv_bfloat162*)&lu;
                    float ev0 = __bfloat162float(__low2bfloat16(hb))
                              + __bfloat162float(__low2bfloat16(lb));
                    float ev1 = __bfloat162float(__high2bfloat16(hb))
                              + __bfloat162float(__high2bfloat16(lb));
                    float v0 = ev0 + frelu(acc[mt][nt][2 * h + 0] + bmv.x);
                    float v1 = ev1 + frelu(acc[mt][nt][2 * h + 1] + bmv.y);
                    uint32_t nh, nl;
                    split2(v0, v1, nh, nl);
                    *(uint32_t*)(smc + OFF_AHI + addr) = nh;
                    *(uint32_t*)(smc + OFF_ALO + addr) = nl;
                    acc[mt][nt][2 * h + 0] = 0.0f;
                    acc[mt][nt][2 * h + 1] = 0.0f;
                }
            }
        }
    }
    asm volatile("cp.async.wait_group 0;" ::: "memory");
    __syncthreads();   // ea2 tile + W_edge complete across warps

    // =========== GEMM 2 ===========
    do_gemm(sb, acc, wm, wn, lane);

    // =========== epilogue 2: out = relu(acc + be) ===========
    {
        const int rq = lane >> 2;
        const int cq = (lane & 3) * 2;
        #pragma unroll
        for (int mt = 0; mt < 4; mt++) {
            int row0 = 64 * wm + 16 * mt + rq;
            #pragma unroll
            for (int nt = 0; nt < 8; nt++) {
                int c = 64 * wn + 8 * nt + cq;
                float2 bev = __ldg((const float2*)(be + c));
                #pragma unroll
                for (int h = 0; h < 2; h++) {
                    int row = row0 + 8 * h;
                    long long ge = e0 + row;
                    if (ge < E) {
                        float2 o;
                        o.x = frelu(acc[mt][nt][2 * h + 0] + bev.x);
                        o.y = frelu(acc[mt][nt][2 * h + 1] + bev.y);
                        *(float2*)(out + ge * NH + c) = o;
                    }
                }
            }
        }
    }
}

// ================= host =================
extern "C" void kernel_launch(void* const* d_in, const int* in_sizes, int n_in,
                              void* d_out, int out_size)
{
    const float* x     = (const float*)d_in[0];
    const float* eattr = (const float*)d_in[1];
    const int*   eidx  = (const int*)d_in[2];   // int32 (JAX canonicalizes int64->int32)
    const float* Wm    = (const float*)d_in[3];
    const float* bm    = (const float*)d_in[4];
    const float* We    = (const float*)d_in[5];
    const float* be    = (const float*)d_in[6];
    float*       out   = (float*)d_out;

    const int E  = in_sizes[2] / 2;
    int n_nodes  = in_sizes[0] / NH;
    if (n_nodes > MAX_NODES) n_nodes = MAX_NODES;

    prep_w_kernel<<<(65536 + 255) / 256, 256>>>(Wm, We);
    long long xt = (long long)n_nodes * NH;
    prep_x_kernel<<<(unsigned)((xt + 255) / 256), 256>>>(x, xt);

    cudaFuncSetAttribute(edge_conv_mma,
                         cudaFuncAttributeMaxDynamicSharedMemorySize, SMEM_TOTAL);

    dim3 grid((E + ET - 1) / ET);
    edge_conv_mma<<<grid, THREADS, SMEM_TOTAL>>>(eattr, eidx, bm, be, out, E, n_nodes);
}

// round 6
// speedup vs baseline: 5.2180x; 1.4795x over previous
#include <cuda_runtime.h>
#include <cuda_fp16.h>
#include <cstdint>

#define NH       128
#define ET       128          // edges per CTA tile
#define THREADS  256

// ---------------- smem layout (bytes) ----------------
#define OFF_RIDX 0             // 128 ints
#define OFF_CIDX 512           // 128 ints
#define OFF_AHI  1024          // 128 rows x 256B (fp16 hi only)
#define OFF_BHI  (OFF_AHI + 32768)
#define OFF_BLO  (OFF_BHI + 32768)
#define SMEM_TOTAL (OFF_BLO + 32768)   // 99328 B -> 2 CTAs/SM

#define MAX_NODES 131072

// ---------------- device scratch (no allocs allowed) ----------------
__device__ uint4 g_xh[MAX_NODES * 16];    // [node][128] fp16 hi (16B chunks, linear)
__device__ uint4 g_wimg_hi[4][2048];      // B'[n][k] fp16, swizzled 32KB images
__device__ uint4 g_wimg_lo[4][2048];

// ---------------- helpers ----------------
__device__ __forceinline__ uint32_t smem_u32(const void* p) {
    uint32_t a;
    asm("{ .reg .u64 t; cvta.to.shared.u64 t, %1; cvt.u32.u64 %0, t; }" : "=r"(a) : "l"(p));
    return a;
}
__device__ __forceinline__ float frelu(float v) { return fmaxf(v, 0.0f); }

__device__ __forceinline__ uint32_t packh2(float a, float b) {
    __half2 h = __floats2half2_rn(a, b);
    return *reinterpret_cast<uint32_t*>(&h);
}

__device__ __forceinline__ void cp16(uint32_t smem_dst, const void* gsrc) {
    asm volatile("cp.async.cg.shared.global [%0], [%1], 16;"
                 :: "r"(smem_dst), "l"(gsrc) : "memory");
}

__device__ __forceinline__ void ldsm_x4(uint32_t (&r)[4], uint32_t addr) {
    asm volatile("ldmatrix.sync.aligned.m8n8.x4.shared.b16 {%0,%1,%2,%3}, [%4];"
        : "=r"(r[0]), "=r"(r[1]), "=r"(r[2]), "=r"(r[3]) : "r"(addr));
}
__device__ __forceinline__ void ldsm_x2(uint32_t (&r)[2], uint32_t addr) {
    asm volatile("ldmatrix.sync.aligned.m8n8.x2.shared.b16 {%0,%1}, [%2];"
        : "=r"(r[0]), "=r"(r[1]) : "r"(addr));
}
__device__ __forceinline__ void mma16816(float (&d)[4], const uint32_t (&a)[4],
                                         const uint32_t (&b)[2]) {
    asm volatile("mma.sync.aligned.m16n8k16.row.col.f32.f16.f16.f32 "
        "{%0,%1,%2,%3}, {%4,%5,%6,%7}, {%8,%9}, {%0,%1,%2,%3};"
        : "+f"(d[0]), "+f"(d[1]), "+f"(d[2]), "+f"(d[3])
        : "r"(a[0]), "r"(a[1]), "r"(a[2]), "r"(a[3]), "r"(b[0]), "r"(b[1]));
}

// ================= prep kernels =================
// B'[n][k] = W[k][n], row n = 256B, 16B chunk c placed at (c ^ (n&7))
__global__ void prep_w_kernel(const float* __restrict__ Wm, const float* __restrict__ We) {
    int idx = blockIdx.x * blockDim.x + threadIdx.x;   // < 4*16384
    if (idx >= 65536) return;
    int mat = idx >> 14, e = idx & 16383;
    int n = e >> 7, k = e & 127;
    float v = (mat < 3) ? Wm[(mat * 128 + k) * 128 + n] : We[k * 128 + n];
    __half hi = __float2half_rn(v);
    __half lo = __float2half_rn(v - __half2float(hi));
    uint32_t pos = (uint32_t)(n * 256 + (((k >> 3) ^ (n & 7)) << 4) + ((k & 7) << 1));
    *(__half*)((char*)g_wimg_hi[mat] + pos) = hi;
    *(__half*)((char*)g_wimg_lo[mat] + pos) = lo;
}

__global__ void prep_x_kernel(const float* __restrict__ x, long long total) {
    long long idx = (long long)blockIdx.x * blockDim.x + threadIdx.x;
    if (idx >= total) return;
    ((__half*)g_xh)[idx] = __float2half_rn(x[idx]);
}

// ================= warp GEMM: acc += A(128x128 fp16) @ (Bhi + Blo)^T ======
// warp-tile 32 (rows, 2 m16) x 64 (cols, 8 n8); 2-term accumulate.
__device__ __forceinline__ void do_gemm(uint32_t sb, float (&acc)[2][8][4],
                                        int wm, int wn, int lane) {
    const int sx = lane & 7;
    const int aR = 32 * wm + sx + ((lane >> 3) & 1) * 8;
    const int aK = (lane >> 4) & 1;
    const int bR = 64 * wn + sx;
    const int bK = (lane >> 3) & 1;
    const uint32_t aBase = sb + OFF_AHI + (uint32_t)aR * 256;
    const uint32_t bBase = sb + OFF_BHI + (uint32_t)bR * 256;

    #pragma unroll 1
    for (int ks = 0; ks < 8; ks++) {
        uint32_t ah[2][4];
        #pragma unroll
        for (int mt = 0; mt < 2; mt++) {
            uint32_t off = (uint32_t)(mt * 16 * 256) + ((uint32_t)((2 * ks + aK) ^ sx) << 4);
            ldsm_x4(ah[mt], aBase + off);
        }
        #pragma unroll
        for (int nt = 0; nt < 8; nt++) {
            uint32_t off = (uint32_t)(nt * 8 * 256) + ((uint32_t)((2 * ks + bK) ^ sx) << 4);
            uint32_t bh[2], bl[2];
            ldsm_x2(bh, bBase + off);
            ldsm_x2(bl, bBase + off + (OFF_BLO - OFF_BHI));
            #pragma unroll
            for (int mt = 0; mt < 2; mt++) {
                mma16816(acc[mt][nt], ah[mt], bh);
                mma16816(acc[mt][nt], ah[mt], bl);
            }
        }
    }
}

// ================= main fused kernel =================
__global__ void __launch_bounds__(THREADS, 2)
edge_conv_mma(const float* __restrict__ eattr,
              const int*   __restrict__ eidx,
              const float* __restrict__ bm,
              const float* __restrict__ be,
              float* __restrict__ out,
              int E, int n_nodes)
{
    extern __shared__ char smc[];
    const uint32_t sb = smem_u32(smc);
    int* ridx = (int*)(smc + OFF_RIDX);
    int* cidx = (int*)(smc + OFF_CIDX);

    const int tid  = threadIdx.x;
    const int wid  = tid >> 5;
    const int lane = tid & 31;
    const int wm   = wid & 3;          // row group (32 edges)
    const int wn   = wid >> 2;         // col group (64 cols)
    const long long e0 = (long long)blockIdx.x * ET;

    if (tid < ET) {
        long long e = e0 + tid; if (e >= E) e = E - 1;
        int r = eidx[e];
        int c = eidx[(long long)E + e];
        ridx[tid] = min(max(r, 0), n_nodes - 1);
        cidx[tid] = min(max(c, 0), n_nodes - 1);
    }

    float acc[2][8][4];
    #pragma unroll
    for (int i = 0; i < 2; i++)
        #pragma unroll
        for (int j = 0; j < 8; j++)
            #pragma unroll
            for (int q = 0; q < 4; q++) acc[i][j][q] = 0.0f;

    // =========== GEMM 1: three K=128 segments ===========
    for (int seg = 0; seg < 3; seg++) {
        __syncthreads();   // prior A/B consumed; idx visible on seg 0
        // --- stage A tile (fp16 hi only, 2048 chunks) ---
        if (seg < 2) {
            const int* idxa = (seg == 0) ? ridx : cidx;
            #pragma unroll
            for (int it = 0; it < 8; it++) {
                int i = tid + it * THREADS;          // < 2048
                int e = i >> 4, c = i & 15;
                int node = idxa[e];
                uint32_t off = (uint32_t)(e * 256 + ((c ^ (e & 7)) << 4));
                cp16(sb + OFF_AHI + off, &g_xh[node * 16 + c]);
            }
        } else {
            #pragma unroll 4
            for (int it = 0; it < 8; it++) {
                int i = tid + it * THREADS;
                int e = i >> 4, c = i & 15;
                long long ge = e0 + e; if (ge >= E) ge = E - 1;
                const float4* s = (const float4*)(eattr + ge * NH + c * 8);
                float4 fa = __ldg(s), fb = __ldg(s + 1);
                uint4 h;
                h.x = packh2(fa.x, fa.y);
                h.y = packh2(fa.z, fa.w);
                h.z = packh2(fb.x, fb.y);
                h.w = packh2(fb.z, fb.w);
                uint32_t off = (uint32_t)(e * 256 + ((c ^ (e & 7)) << 4));
                *(uint4*)(smc + OFF_AHI + off) = h;
            }
        }
        // --- stage B tile (cp.async of preswizzled images) ---
        #pragma unroll
        for (int it = 0; it < 8; it++) {
            int i = tid + it * THREADS;              // < 2048
            cp16(sb + OFF_BHI + i * 16, &g_wimg_hi[seg][i]);
            cp16(sb + OFF_BLO + i * 16, &g_wimg_lo[seg][i]);
        }
        asm volatile("cp.async.commit_group;" ::: "memory");
        asm volatile("cp.async.wait_group 0;" ::: "memory");
        __syncthreads();
        do_gemm(sb, acc, wm, wn, lane);
    }

    __syncthreads();   // all warps done reading A/B of GEMM1

    // --- stage B = W_edge images (async; overlaps epilogue 1) ---
    #pragma unroll
    for (int it = 0; it < 8; it++) {
        int i = tid + it * THREADS;
        cp16(sb + OFF_BHI + i * 16, &g_wimg_hi[3][i]);
        cp16(sb + OFF_BLO + i * 16, &g_wimg_lo[3][i]);
    }
    asm volatile("cp.async.commit_group;" ::: "memory");

    // ==== epilogue 1: ea2 = eattr + relu(msg + bm), RMW A tile in place (fp16) ====
    {
        const int rq = lane >> 2;          // 0..7
        const int cq = (lane & 3) * 2;     // 0,2,4,6
        #pragma unroll
        for (int mt = 0; mt < 2; mt++) {
            int row0 = 32 * wm + 16 * mt + rq;
            #pragma unroll
            for (int nt = 0; nt < 8; nt++) {
                int c = 64 * wn + 8 * nt + cq;
                float2 bmv = __ldg((const float2*)(bm + c));
                #pragma unroll
                for (int h = 0; h < 2; h++) {
                    int row = row0 + 8 * h;
                    uint32_t addr = (uint32_t)(row * 256 +
                                    (((c >> 3) ^ (row & 7)) << 4) + ((c & 7) << 1));
                    uint32_t hu = *(uint32_t*)(smc + OFF_AHI + addr);
                    __half2 hb = *(__half2*)&hu;
                    float ev0 = __half2float(__low2half(hb));
                    float ev1 = __half2float(__high2half(hb));
                    float v0 = ev0 + frelu(acc[mt][nt][2 * h + 0] + bmv.x);
                    float v1 = ev1 + frelu(acc[mt][nt][2 * h + 1] + bmv.y);
                    *(uint32_t*)(smc + OFF_AHI + addr) = packh2(v0, v1);
                    acc[mt][nt][2 * h + 0] = 0.0f;
                    acc[mt][nt][2 * h + 1] = 0.0f;
                }
            }
        }
    }
    asm volatile("cp.async.wait_group 0;" ::: "memory");
    __syncthreads();   // ea2 tile + W_edge complete across warps

    // =========== GEMM 2 ===========
    do_gemm(sb, acc, wm, wn, lane);

    // =========== epilogue 2: out = relu(acc + be) ===========
    {
        const int rq = lane >> 2;
        const int cq = (lane & 3) * 2;
        #pragma unroll
        for (int mt = 0; mt < 2; mt++) {
            int row0 = 32 * wm + 16 * mt + rq;
            #pragma unroll
            for (int nt = 0; nt < 8; nt++) {
                int c = 64 * wn + 8 * nt + cq;
                float2 bev = __ldg((const float2*)(be + c));
                #pragma unroll
                for (int h = 0; h < 2; h++) {
                    int row = row0 + 8 * h;
                    long long ge = e0 + row;
                    if (ge < E) {
                        float2 o;
                        o.x = frelu(acc[mt][nt][2 * h + 0] + bev.x);
                        o.y = frelu(acc[mt][nt][2 * h + 1] + bev.y);
                        *(float2*)(out + ge * NH + c) = o;
                    }
                }
            }
        }
    }
}

// ================= host =================
extern "C" void kernel_launch(void* const* d_in, const int* in_sizes, int n_in,
                              void* d_out, int out_size)
{
    const float* x     = (const float*)d_in[0];
    const float* eattr = (const float*)d_in[1];
    const int*   eidx  = (const int*)d_in[2];   // int32 (JAX canonicalizes int64->int32)
    const float* Wm    = (const float*)d_in[3];
    const float* bm    = (const float*)d_in[4];
    const float* We    = (const float*)d_in[5];
    const float* be    = (const float*)d_in[6];
    float*       out   = (float*)d_out;

    const int E  = in_sizes[2] / 2;
    int n_nodes  = in_sizes[0] / NH;
    if (n_nodes > MAX_NODES) n_nodes = MAX_NODES;

    prep_w_kernel<<<(65536 + 255) / 256, 256>>>(Wm, We);
    long long xt = (long long)n_nodes * NH;
    prep_x_kernel<<<(unsigned)((xt + 255) / 256), 256>>>(x, xt);

    cudaFuncSetAttribute(edge_conv_mma,
                         cudaFuncAttributeMaxDynamicSharedMemorySize, SMEM_TOTAL);

    dim3 grid((E + ET - 1) / ET);
    edge_conv_mma<<<grid, THREADS, SMEM_TOTAL>>>(eattr, eidx, bm, be, out, E, n_nodes);
}